// round 1
// baseline (speedup 1.0000x reference)
#include <cuda_runtime.h>
#include <math.h>

// IDXST_IDCT 4096x4096 via Makhoul single-length FFT:
//   c[k] = x[k]*expk[k];  A = DFT_4096(c)
//   idct:  out[2m] = Re A[m],  out[2N-1-2m] = Re A[m]
//   idxst: out[2m] = -Im A[m], out[2N-1-2m] = +Im A[m]
// Pipeline: rowFFT(x, expkN, Re) -> T -> rowFFT(., expkM, +/-Im) -> T

#define LROW 4096
#define FFT_THREADS 1024
#define TW_COUNT 1024
#define SMEM_FLOAT2 (2 * LROW + TW_COUNT)

__device__ float2 g_tw[TW_COUNT];
__device__ float g_buf0[(unsigned long long)LROW * LROW];
__device__ float g_buf1[(unsigned long long)LROW * LROW];

__device__ __forceinline__ float2 cmul(float2 a, float2 b) {
    return make_float2(a.x * b.x - a.y * b.y, a.x * b.y + a.y * b.x);
}
__device__ __forceinline__ float2 cadd(float2 a, float2 b) {
    return make_float2(a.x + b.x, a.y + b.y);
}
__device__ __forceinline__ float2 csub(float2 a, float2 b) {
    return make_float2(a.x - b.x, a.y - b.y);
}

__global__ void init_twiddles_kernel() {
    int k = threadIdx.x;  // 1024 threads
    double s, c;
    sincospi(-2.0 * (double)k / (double)LROW, &s, &c);
    g_tw[k] = make_float2((float)c, (float)s);
}

// MODE 0: IDCT (Re with reorder). MODE 1: IDXST (-Im even, +Im odd, with reorder).
template <int MODE>
__global__ __launch_bounds__(FFT_THREADS)
void fft_row_kernel(const float* __restrict__ in, const float2* __restrict__ expk,
                    float* __restrict__ out) {
    extern __shared__ float2 sm[];
    float2* bufA = sm;
    float2* bufB = sm + LROW;
    float2* tw = sm + 2 * LROW;

    const int tid = threadIdx.x;
    const unsigned long long row = blockIdx.x;
    const float* __restrict__ xin = in + row * LROW;

    tw[tid] = g_tw[tid];

#pragma unroll
    for (int i = 0; i < 4; i++) {
        int k = tid + i * FFT_THREADS;
        float xv = xin[k];
        float2 e = expk[k];
        bufA[k] = make_float2(xv * e.x, xv * e.y);
    }
    __syncthreads();

    // 6 radix-4 Stockham (DIF, autosort) stages. s = 4^st, m = 1024/4^st (n/4).
    // s*m == 1024 at every stage. Twiddle w1 = e^{-2pij*p/n} = g_tw[p*s].
    float2* X = bufA;
    float2* Y = bufB;
#pragma unroll
    for (int st = 0; st < 6; st++) {
        const int s = 1 << (2 * st);
        const int q = tid & (s - 1);
        const int ps = tid - q;    // p*s  (< 1024)
        const int p4s = ps << 2;   // 4*p*s

        float2 a = X[q + ps];
        float2 b = X[q + ps + 1024];
        float2 c = X[q + ps + 2048];
        float2 d = X[q + ps + 3072];

        float2 apc = cadd(a, c), amc = csub(a, c);
        float2 bpd = cadd(b, d), bmd = csub(b, d);
        float2 jb = make_float2(-bmd.y, bmd.x);  // j*(b-d)

        float2 w1 = tw[ps];
        float2 w2 = cmul(w1, w1);
        float2 w3 = cmul(w1, w2);

        Y[q + p4s]         = cadd(apc, bpd);
        Y[q + p4s + s]     = cmul(w1, csub(amc, jb));
        Y[q + p4s + 2 * s] = cmul(w2, csub(apc, bpd));
        Y[q + p4s + 3 * s] = cmul(w3, cadd(amc, jb));
        __syncthreads();
        float2* t = X; X = Y; Y = t;
    }
    // After 6 stages result (natural order) is back in bufA == X.

    float* __restrict__ o = out + row * LROW;
    const int n0 = tid << 2;
    float vals[4];
#pragma unroll
    for (int j = 0; j < 4; j++) {
        int nn = n0 + j;
        int m = (nn & 1) ? ((2 * LROW - 1 - nn) >> 1) : (nn >> 1);
        float2 v = X[m];
        if (MODE == 0)
            vals[j] = v.x;
        else
            vals[j] = (nn & 1) ? v.y : -v.y;
    }
    *reinterpret_cast<float4*>(o + n0) = make_float4(vals[0], vals[1], vals[2], vals[3]);
}

__global__ void transpose_kernel(const float* __restrict__ in, float* __restrict__ out) {
    __shared__ float tile[32][33];
    int x = blockIdx.x * 32 + threadIdx.x;
    int y0 = blockIdx.y * 32;
#pragma unroll
    for (int j = threadIdx.y; j < 32; j += 8)
        tile[j][threadIdx.x] = in[(unsigned long long)(y0 + j) * LROW + x];
    __syncthreads();
    int x2 = blockIdx.y * 32 + threadIdx.x;
    int y2 = blockIdx.x * 32;
#pragma unroll
    for (int j = threadIdx.y; j < 32; j += 8)
        out[(unsigned long long)(y2 + j) * LROW + x2] = tile[threadIdx.x][j];
}

extern "C" void kernel_launch(void* const* d_in, const int* in_sizes, int n_in,
                              void* d_out, int out_size) {
    const float* x = (const float*)d_in[0];
    const float2* expkM = (const float2*)d_in[1];
    const float2* expkN = (const float2*)d_in[2];
    float* out = (float*)d_out;

    float *buf0, *buf1;
    cudaGetSymbolAddress((void**)&buf0, g_buf0);
    cudaGetSymbolAddress((void**)&buf1, g_buf1);

    size_t smem = (size_t)SMEM_FLOAT2 * sizeof(float2);  // 73728 B
    cudaFuncSetAttribute(fft_row_kernel<0>, cudaFuncAttributeMaxDynamicSharedMemorySize,
                         (int)smem);
    cudaFuncSetAttribute(fft_row_kernel<1>, cudaFuncAttributeMaxDynamicSharedMemorySize,
                         (int)smem);

    dim3 tb(32, 8), tg(LROW / 32, LROW / 32);

    init_twiddles_kernel<<<1, TW_COUNT>>>();
    // t = idct_rows(x, expkN)
    fft_row_kernel<0><<<LROW, FFT_THREADS, smem>>>(x, expkN, buf0);
    // tT
    transpose_kernel<<<tg, tb>>>(buf0, buf1);
    // yT = idxst_rows(tT, expkM)
    fft_row_kernel<1><<<LROW, FFT_THREADS, smem>>>(buf1, expkM, buf0);
    // y
    transpose_kernel<<<tg, tb>>>(buf0, out);
}

// round 2
// speedup vs baseline: 1.8955x; 1.8955x over previous
#include <cuda_runtime.h>
#include <math.h>

// IDXST_IDCT 4096x4096 via Makhoul single-length FFT, register radix-16.
//   c[k] = x[k]*expk[k];  A = DFT_4096(c)
//   idct:  m<2048: out[2m]=Re A[m];  m>=2048: out[8191-2m]=Re A[m]
//   idxst: m<2048: out[2m]=-Im A[m]; m>=2048: out[8191-2m]=+Im A[m]
// Pipeline: rowFFT(x,expkN,Re) -> T -> rowFFT(.,expkM,Im) -> T

#define LROW 4096
#define FFT_T 256
#define PADSZ 4352  // 4096 + 4096/16

__device__ float2 g_twS0[256];  // e^{-2pi j t/4096}
__device__ float2 g_twS1[16];   // e^{-2pi j p/256}
__device__ float g_buf0[(size_t)LROW * LROW];
__device__ float g_buf1[(size_t)LROW * LROW];

__device__ __forceinline__ float2 cmul(float2 a, float2 b) {
    return make_float2(a.x * b.x - a.y * b.y, a.x * b.y + a.y * b.x);
}
__device__ __forceinline__ float2 cadd(float2 a, float2 b) {
    return make_float2(a.x + b.x, a.y + b.y);
}
__device__ __forceinline__ float2 csub(float2 a, float2 b) {
    return make_float2(a.x - b.x, a.y - b.y);
}

// e^{-2pi j k/16}, k=0..9 (only 0..9 reachable as i*p, i,p<4)
__constant__ float2 c_tw16[10] = {
    {1.f, 0.f},
    {0.92387953251128674f, -0.38268343236508978f},
    {0.70710678118654757f, -0.70710678118654757f},
    {0.38268343236508978f, -0.92387953251128674f},
    {0.f, -1.f},
    {-0.38268343236508978f, -0.92387953251128674f},
    {-0.70710678118654757f, -0.70710678118654757f},
    {-0.92387953251128674f, -0.38268343236508978f},
    {-1.f, 0.f},
    {-0.92387953251128674f, 0.38268343236508978f}};

__global__ void init_twiddles_kernel() {
    int t = threadIdx.x;  // 256
    double s, c;
    sincospi(-(double)t / 2048.0, &s, &c);
    g_twS0[t] = make_float2((float)c, (float)s);
    if (t < 16) {
        sincospi(-(double)t / 128.0, &s, &c);
        g_twS1[t] = make_float2((float)c, (float)s);
    }
}

// 16-point DFT, natural in -> natural out, two radix-4 Stockham stages in regs.
__device__ __forceinline__ void fft16(float2 r[16]) {
    float2 y[16];
#pragma unroll
    for (int p = 0; p < 4; p++) {
        float2 a = r[p], b = r[p + 4], c = r[p + 8], d = r[p + 12];
        float2 apc = cadd(a, c), amc = csub(a, c);
        float2 bpd = cadd(b, d), bmd = csub(b, d);
        float2 jb = make_float2(-bmd.y, bmd.x);
        float2 o0 = cadd(apc, bpd);
        float2 o1 = csub(amc, jb);
        float2 o2 = csub(apc, bpd);
        float2 o3 = cadd(amc, jb);
        y[4 * p + 0] = o0;
        y[4 * p + 1] = (p == 0) ? o1 : cmul(o1, c_tw16[p]);
        y[4 * p + 2] = (p == 0) ? o2 : cmul(o2, c_tw16[2 * p]);
        y[4 * p + 3] = (p == 0) ? o3 : cmul(o3, c_tw16[3 * p]);
    }
#pragma unroll
    for (int q = 0; q < 4; q++) {
        float2 a = y[q], b = y[q + 4], c = y[q + 8], d = y[q + 12];
        float2 apc = cadd(a, c), amc = csub(a, c);
        float2 bpd = cadd(b, d), bmd = csub(b, d);
        float2 jb = make_float2(-bmd.y, bmd.x);
        r[q] = cadd(apc, bpd);
        r[q + 4] = csub(amc, jb);
        r[q + 8] = csub(apc, bpd);
        r[q + 12] = cadd(amc, jb);
    }
}

// MODE 0: IDCT (Re).  MODE 1: IDXST (-Im for m<2048, +Im for m>=2048).
template <int MODE>
__global__ __launch_bounds__(FFT_T, 3) void fft_row_kernel(
    const float* __restrict__ in, const float2* __restrict__ expk,
    float* __restrict__ out) {
    extern __shared__ float sm[];
    float* sre = sm;
    float* sim = sm + PADSZ;

    const int t = threadIdx.x;
    const size_t row = blockIdx.x;
    const float* __restrict__ xin = in + row * LROW;

    float2 r[16];
    // Load: element t + 256*i, times expk (coalesced 4B/8B reads).
#pragma unroll
    for (int i = 0; i < 16; i++) {
        int k = t + 256 * i;
        float xv = xin[k];
        float2 e = expk[k];
        r[i] = make_float2(xv * e.x, xv * e.y);
    }

    // ---- big stage 0 (Ls=1, p=t): FFT16, twiddle w^i (w=e^{-2pij t/4096}),
    //      write Y[16t+i] at padded slot 17t+i.
    fft16(r);
    {
        float2 w = g_twS0[t];
        float2 cur = w;
        sre[17 * t] = r[0].x;
        sim[17 * t] = r[0].y;
#pragma unroll
        for (int i = 1; i < 16; i++) {
            float2 v = cmul(r[i], cur);
            cur = cmul(cur, w);
            sre[17 * t + i] = v.x;
            sim[17 * t + i] = v.y;
        }
    }
    __syncthreads();

    // ---- read idx = t + 256 i -> slot t + (t>>4) + 272 i
    const int rbase = t + (t >> 4);
#pragma unroll
    for (int i = 0; i < 16; i++)
        r[i] = make_float2(sre[rbase + 272 * i], sim[rbase + 272 * i]);
    __syncthreads();

    // ---- big stage 1 (Ls=16): FFT16, twiddle w^i (w=e^{-2pij p/256}, p=t>>4),
    //      write Y[q + 256p + 16i] at slot q + 272p + 17i.
    fft16(r);
    {
        const int q = t & 15;
        const int p = t >> 4;
        const int wb = q + 272 * p;
        float2 w = g_twS1[p];
        float2 cur = w;
        sre[wb] = r[0].x;
        sim[wb] = r[0].y;
#pragma unroll
        for (int i = 1; i < 16; i++) {
            float2 v = cmul(r[i], cur);
            cur = cmul(cur, w);
            sre[wb + 17 * i] = v.x;
            sim[wb + 17 * i] = v.y;
        }
    }
    __syncthreads();

#pragma unroll
    for (int i = 0; i < 16; i++)
        r[i] = make_float2(sre[rbase + 272 * i], sim[rbase + 272 * i]);
    __syncthreads();

    // ---- big stage 2 (Ls=256, p=0): FFT16, no twiddle; r[i] = A[t + 256 i].
    fft16(r);

    // ---- reorder to output positions in smem (real values), then coalesced f4 out.
#pragma unroll
    for (int i = 0; i < 16; i++) {
        int m = t + 256 * i;
        float v;
        if (MODE == 0)
            v = r[i].x;
        else
            v = (i < 8) ? -r[i].y : r[i].y;  // i<8 <=> m<2048
        int n = (i < 8) ? (2 * m) : (8191 - 2 * m);
        sre[n] = v;
    }
    __syncthreads();

    float4* __restrict__ o4 = reinterpret_cast<float4*>(out + row * LROW);
#pragma unroll
    for (int i = 0; i < 4; i++) {
        float4 v = *reinterpret_cast<float4*>(&sre[4 * t + 1024 * i]);
        o4[t + 256 * i] = v;
    }
}

#define TTILE 64
__global__ __launch_bounds__(256) void transpose_kernel(
    const float* __restrict__ in, float* __restrict__ out) {
    __shared__ float tile[TTILE][TTILE + 1];
    const int x0 = blockIdx.x * TTILE, y0 = blockIdx.y * TTILE;
    const int tx = threadIdx.x, ty = threadIdx.y;  // (16,16)
#pragma unroll
    for (int j = 0; j < 4; j++) {
        int rowi = y0 + ty + 16 * j;
        float4 v = *reinterpret_cast<const float4*>(&in[(size_t)rowi * LROW + x0 + 4 * tx]);
        tile[4 * tx + 0][ty + 16 * j] = v.x;
        tile[4 * tx + 1][ty + 16 * j] = v.y;
        tile[4 * tx + 2][ty + 16 * j] = v.z;
        tile[4 * tx + 3][ty + 16 * j] = v.w;
    }
    __syncthreads();
#pragma unroll
    for (int j = 0; j < 4; j++) {
        int rowo = x0 + ty + 16 * j;
        float4 v = make_float4(tile[ty + 16 * j][4 * tx + 0], tile[ty + 16 * j][4 * tx + 1],
                               tile[ty + 16 * j][4 * tx + 2], tile[ty + 16 * j][4 * tx + 3]);
        *reinterpret_cast<float4*>(&out[(size_t)rowo * LROW + y0 + 4 * tx]) = v;
    }
}

extern "C" void kernel_launch(void* const* d_in, const int* in_sizes, int n_in,
                              void* d_out, int out_size) {
    const float* x = (const float*)d_in[0];
    const float2* expkM = (const float2*)d_in[1];
    const float2* expkN = (const float2*)d_in[2];
    float* out = (float*)d_out;

    float *buf0, *buf1;
    cudaGetSymbolAddress((void**)&buf0, g_buf0);
    cudaGetSymbolAddress((void**)&buf1, g_buf1);

    const size_t smem = 2 * PADSZ * sizeof(float);  // 34816 B
    dim3 tb(16, 16), tg(LROW / TTILE, LROW / TTILE);

    init_twiddles_kernel<<<1, 256>>>();
    fft_row_kernel<0><<<LROW, FFT_T, smem>>>(x, expkN, buf0);   // t = idct_rows(x)
    transpose_kernel<<<tg, tb>>>(buf0, buf1);                   // t^T
    fft_row_kernel<1><<<LROW, FFT_T, smem>>>(buf1, expkM, buf0);// y^T = idxst_rows(t^T)
    transpose_kernel<<<tg, tb>>>(buf0, out);                    // y
}

// round 3
// speedup vs baseline: 2.1103x; 1.1133x over previous
#include <cuda_runtime.h>
#include <math.h>

// IDXST_IDCT 4096x4096 via Makhoul single-length FFT, register radix-16.
//   c[k] = x[k]*expk[k];  A = DFT_4096(c)
//   idct:  m<2048: out[2m]=Re A[m];  m>=2048: out[8191-2m]=Re A[m]
//   idxst: m<2048: out[2m]=-Im A[m]; m>=2048: out[8191-2m]=+Im A[m]
// Pipeline: rowFFT(x,expkN,Re) -> T -> rowFFT(.,expkM,Im) -> T

#define LROW 4096
#define FFT_T 256
#define PADSZ 4352  // 4096 + 4096/16 (float2 slots)

__device__ float2 g_twS0[256];  // e^{-2pi j t/4096}
__device__ float2 g_twS1[16];   // e^{-2pi j p/256}
__device__ float g_buf0[(size_t)LROW * LROW];
__device__ float g_buf1[(size_t)LROW * LROW];

__device__ __forceinline__ float2 cmul(float2 a, float2 b) {
    return make_float2(a.x * b.x - a.y * b.y, a.x * b.y + a.y * b.x);
}
__device__ __forceinline__ float2 cadd(float2 a, float2 b) {
    return make_float2(a.x + b.x, a.y + b.y);
}
__device__ __forceinline__ float2 csub(float2 a, float2 b) {
    return make_float2(a.x - b.x, a.y - b.y);
}

// e^{-2pi j k/16}, k=0..9 (only 0..9 reachable as i*p, i,p<4)
__constant__ float2 c_tw16[10] = {
    {1.f, 0.f},
    {0.92387953251128674f, -0.38268343236508978f},
    {0.70710678118654757f, -0.70710678118654757f},
    {0.38268343236508978f, -0.92387953251128674f},
    {0.f, -1.f},
    {-0.38268343236508978f, -0.92387953251128674f},
    {-0.70710678118654757f, -0.70710678118654757f},
    {-0.92387953251128674f, -0.38268343236508978f},
    {-1.f, 0.f},
    {-0.92387953251128674f, 0.38268343236508978f}};

__global__ void init_twiddles_kernel() {
    int t = threadIdx.x;  // 256
    double s, c;
    sincospi(-(double)t / 2048.0, &s, &c);
    g_twS0[t] = make_float2((float)c, (float)s);
    if (t < 16) {
        sincospi(-(double)t / 128.0, &s, &c);
        g_twS1[t] = make_float2((float)c, (float)s);
    }
}

// 16-point DFT, natural in -> natural out, two radix-4 Stockham stages in regs.
__device__ __forceinline__ void fft16(float2 r[16]) {
    float2 y[16];
#pragma unroll
    for (int p = 0; p < 4; p++) {
        float2 a = r[p], b = r[p + 4], c = r[p + 8], d = r[p + 12];
        float2 apc = cadd(a, c), amc = csub(a, c);
        float2 bpd = cadd(b, d), bmd = csub(b, d);
        float2 jb = make_float2(-bmd.y, bmd.x);
        float2 o0 = cadd(apc, bpd);
        float2 o1 = csub(amc, jb);
        float2 o2 = csub(apc, bpd);
        float2 o3 = cadd(amc, jb);
        y[4 * p + 0] = o0;
        y[4 * p + 1] = (p == 0) ? o1 : cmul(o1, c_tw16[p]);
        y[4 * p + 2] = (p == 0) ? o2 : cmul(o2, c_tw16[2 * p]);
        y[4 * p + 3] = (p == 0) ? o3 : cmul(o3, c_tw16[3 * p]);
    }
#pragma unroll
    for (int q = 0; q < 4; q++) {
        float2 a = y[q], b = y[q + 4], c = y[q + 8], d = y[q + 12];
        float2 apc = cadd(a, c), amc = csub(a, c);
        float2 bpd = cadd(b, d), bmd = csub(b, d);
        float2 jb = make_float2(-bmd.y, bmd.x);
        r[q] = cadd(apc, bpd);
        r[q + 4] = csub(amc, jb);
        r[q + 8] = csub(apc, bpd);
        r[q + 12] = cadd(amc, jb);
    }
}

// Store r[i]*w^i to dst[i*stride] with a depth-4 twiddle power tree.
__device__ __forceinline__ void twiddle_store(float2* dst, int stride,
                                              const float2 r[16], float2 w1) {
    float2 w2 = cmul(w1, w1);
    float2 w3 = cmul(w2, w1);
    float2 w4 = cmul(w2, w2);
    float2 w8 = cmul(w4, w4);
    dst[0] = r[0];
    dst[1 * stride] = cmul(r[1], w1);
    dst[2 * stride] = cmul(r[2], w2);
    dst[3 * stride] = cmul(r[3], w3);
    dst[4 * stride] = cmul(r[4], w4);
    dst[5 * stride] = cmul(r[5], cmul(w4, w1));
    dst[6 * stride] = cmul(r[6], cmul(w4, w2));
    dst[7 * stride] = cmul(r[7], cmul(w4, w3));
    dst[8 * stride] = cmul(r[8], w8);
    dst[9 * stride] = cmul(r[9], cmul(w8, w1));
    dst[10 * stride] = cmul(r[10], cmul(w8, w2));
    dst[11 * stride] = cmul(r[11], cmul(w8, w3));
    dst[12 * stride] = cmul(r[12], cmul(w8, w4));
    dst[13 * stride] = cmul(r[13], cmul(w8, cmul(w4, w1)));
    dst[14 * stride] = cmul(r[14], cmul(w8, cmul(w4, w2)));
    dst[15 * stride] = cmul(r[15], cmul(w8, cmul(w4, w3)));
}

// MODE 0: IDCT (Re).  MODE 1: IDXST (-Im for m<2048, +Im for m>=2048).
template <int MODE>
__global__ __launch_bounds__(FFT_T, 3) void fft_row_kernel(
    const float* __restrict__ in, const float2* __restrict__ expk,
    float* __restrict__ out) {
    extern __shared__ float2 sm2[];

    const int t = threadIdx.x;
    const size_t row = blockIdx.x;
    const float* __restrict__ xin = in + row * LROW;

    float2 r[16];
#pragma unroll
    for (int i = 0; i < 16; i++) {
        int k = t + 256 * i;
        float xv = xin[k];
        float2 e = expk[k];
        r[i] = make_float2(xv * e.x, xv * e.y);
    }

    // ---- big stage 0 (Ls=1, p=t): FFT16, twiddle w^i (w=e^{-2pij t/4096}),
    //      write Y[16t+i] at padded float2 slot 17t+i (conflict-free at 8B words).
    fft16(r);
    twiddle_store(&sm2[17 * t], 1, r, g_twS0[t]);
    __syncthreads();

    // ---- read idx = t + 256 i -> slot t + (t>>4) + 272 i (conflict-free)
    const int rbase = t + (t >> 4);
#pragma unroll
    for (int i = 0; i < 16; i++) r[i] = sm2[rbase + 272 * i];
    __syncthreads();

    // ---- big stage 1 (Ls=16): FFT16, twiddle w^i (w=e^{-2pij p/256}, p=t>>4),
    //      write Y[q + 256p + 16i] at slot q + 272p + 17i (conflict-free).
    fft16(r);
    twiddle_store(&sm2[(t & 15) + 272 * (t >> 4)], 17, r, g_twS1[t >> 4]);
    __syncthreads();

#pragma unroll
    for (int i = 0; i < 16; i++) r[i] = sm2[rbase + 272 * i];
    __syncthreads();

    // ---- big stage 2 (Ls=256, p=0): FFT16, no twiddle; r[i] = A[t + 256 i].
    fft16(r);

    // ---- reorder real outputs in smem, then coalesced float4 stores.
    float* sref = reinterpret_cast<float*>(sm2);
#pragma unroll
    for (int i = 0; i < 16; i++) {
        int m = t + 256 * i;
        float v;
        if (MODE == 0)
            v = r[i].x;
        else
            v = (i < 8) ? -r[i].y : r[i].y;  // i<8 <=> m<2048
        int n = (i < 8) ? (2 * m) : (8191 - 2 * m);
        sref[n] = v;
    }
    __syncthreads();

    float4* __restrict__ o4 = reinterpret_cast<float4*>(out + row * LROW);
#pragma unroll
    for (int i = 0; i < 4; i++) {
        float4 v = *reinterpret_cast<float4*>(&sref[4 * t + 1024 * i]);
        o4[t + 256 * i] = v;
    }
}

#define TTILE 64
__global__ __launch_bounds__(256) void transpose_kernel(
    const float* __restrict__ in, float* __restrict__ out) {
    __shared__ float tile[TTILE][TTILE + 1];
    const int x0 = blockIdx.x * TTILE, y0 = blockIdx.y * TTILE;
    const int tx = threadIdx.x, ty = threadIdx.y;  // (16,16)
#pragma unroll
    for (int j = 0; j < 4; j++) {
        int rowi = y0 + ty + 16 * j;
        float4 v = *reinterpret_cast<const float4*>(&in[(size_t)rowi * LROW + x0 + 4 * tx]);
        tile[4 * tx + 0][ty + 16 * j] = v.x;
        tile[4 * tx + 1][ty + 16 * j] = v.y;
        tile[4 * tx + 2][ty + 16 * j] = v.z;
        tile[4 * tx + 3][ty + 16 * j] = v.w;
    }
    __syncthreads();
#pragma unroll
    for (int j = 0; j < 4; j++) {
        int rowo = x0 + ty + 16 * j;
        float4 v = make_float4(tile[ty + 16 * j][4 * tx + 0], tile[ty + 16 * j][4 * tx + 1],
                               tile[ty + 16 * j][4 * tx + 2], tile[ty + 16 * j][4 * tx + 3]);
        *reinterpret_cast<float4*>(&out[(size_t)rowo * LROW + y0 + 4 * tx]) = v;
    }
}

extern "C" void kernel_launch(void* const* d_in, const int* in_sizes, int n_in,
                              void* d_out, int out_size) {
    const float* x = (const float*)d_in[0];
    const float2* expkM = (const float2*)d_in[1];
    const float2* expkN = (const float2*)d_in[2];
    float* out = (float*)d_out;

    float *buf0, *buf1;
    cudaGetSymbolAddress((void**)&buf0, g_buf0);
    cudaGetSymbolAddress((void**)&buf1, g_buf1);

    const size_t smem = (size_t)PADSZ * sizeof(float2);  // 34816 B
    dim3 tb(16, 16), tg(LROW / TTILE, LROW / TTILE);

    init_twiddles_kernel<<<1, 256>>>();
    fft_row_kernel<0><<<LROW, FFT_T, smem>>>(x, expkN, buf0);    // t = idct_rows(x)
    transpose_kernel<<<tg, tb>>>(buf0, buf1);                    // t^T
    fft_row_kernel<1><<<LROW, FFT_T, smem>>>(buf1, expkM, buf0); // y^T = idxst_rows(t^T)
    transpose_kernel<<<tg, tb>>>(buf0, out);                     // y
}